// round 10
// baseline (speedup 1.0000x reference)
#include <cuda_runtime.h>
#include <cuda_bf16.h>
#include <cstddef>

// ---------------------------------------------------------------------------
// Problem constants
// ---------------------------------------------------------------------------
static const int NPTS  = 65536;   // nodes
static const int HID   = 512;
static const int HH    = 1024;    // HEADS*HID
static const int KVSPL = 16;      // split-K factor for K^T V

// Dynamic smem sizes (bytes)
static const int SMEM_NN   = (2 * 2560 + 2 * 4224) * 4;  // 54272: As[128][20]x2 + Bs[16][264]x2
static const int SMEM_KV   = (2 * 2176 + 2 * 4224) * 4;  // 51200: As[16][136]x2 + Bs[16][264]x2

// ---------------------------------------------------------------------------
// Scratch (device globals; no allocation allowed).
// ---------------------------------------------------------------------------
__device__ float g_qk  [65536u * 1024u];      // K, later overwritten by Q (256MB)
__device__ float g_v   [65536u * 1024u];      // V; head-0 half later holds attn (256MB)
__device__ float g_h   [65536u * 512u];       // fc0 output (layer-0 prev)   (128MB)
__device__ float g_kvp [32u * 512u * 512u];   // split-K partials             (32MB)
__device__ float g_kvs [2u * 512u * 512u];    // K^T V per head               (2MB)
__device__ float g_ksp [512u * 1024u];        // per-block column-sum partials (2MB)
__device__ float g_ks  [1024u];
__device__ float g_red [8192u];
__device__ float g_scal[2u];
__device__ float g_qdp [4u * 65536u];         // per-ntile q.ks row partials  (1MB)
__device__ float g_inv [2u * 65536u];         // per-row per-head 1/denominator

// ---------------------------------------------------------------------------
// Helpers
// ---------------------------------------------------------------------------
__device__ __forceinline__ unsigned tf32_of(float f) {
    unsigned u;
    asm("cvt.rna.tf32.f32 %0, %1;" : "=r"(u) : "f"(f));
    return u;
}

__device__ __forceinline__ void mma_tf32(float c[4], const unsigned a[4],
                                         const unsigned b[2]) {
    asm volatile(
        "mma.sync.aligned.m16n8k8.row.col.f32.tf32.tf32.f32 "
        "{%0,%1,%2,%3},{%4,%5,%6,%7},{%8,%9},{%0,%1,%2,%3};\n"
        : "+f"(c[0]), "+f"(c[1]), "+f"(c[2]), "+f"(c[3])
        : "r"(a[0]), "r"(a[1]), "r"(a[2]), "r"(a[3]), "r"(b[0]), "r"(b[1]));
}

__device__ __forceinline__ float block_reduce_sum(float v, float* sm) {
    int tid = threadIdx.x;
    int lane = tid & 31, wid = tid >> 5;
    #pragma unroll
    for (int o = 16; o > 0; o >>= 1) v += __shfl_down_sync(0xffffffffu, v, o);
    __syncthreads();
    if (lane == 0) sm[wid] = v;
    __syncthreads();
    if (tid == 0) {
        float s = 0.f;
        #pragma unroll
        for (int i = 0; i < 8; i++) s += sm[i];
        sm[0] = s;
    }
    __syncthreads();
    return sm[0];
}

// ===========================================================================
// v3 GEMM core: block tile 128(M) x 256(N), BK=16, 256 threads,
// DOUBLE-BUFFERED smem stages (one __syncthreads per tile; STS+LDG overlap MMA).
// 8 warps as 2(M) x 4(N); warp tile 64x64 -> 4x8 m16n8k8 fragments.
// ===========================================================================
__global__ __launch_bounds__(256) void gemm_nn_v3(
    const float* __restrict__ A, const float* __restrict__ B,
    const float* __restrict__ bias, float* __restrict__ C,
    int M, int N, int K, int lda, int ldb, int ldc,
    float* __restrict__ ss_out,
    float* __restrict__ colsum_out,
    const float* __restrict__ ksvec,
    float* __restrict__ qdp_out)
{
    extern __shared__ unsigned dsm[];
    unsigned* AsS[2] = { dsm,        dsm + 2560 };          // [128][20] each
    unsigned* BsS[2] = { dsm + 5120, dsm + 5120 + 4224 };   // [16][264] each
    float* epism = (float*)dsm;      // post-mainloop alias of stage smem
    __shared__ float rsm[8];

    const int tid = threadIdx.x;
    const int lane = tid & 31;
    const int wid = tid >> 5;
    const int gid = lane >> 2, tig = lane & 3;
    const int warp_m = (wid & 1) * 64;
    const int warp_n = (wid >> 1) * 64;
    const int m0 = blockIdx.y * 128;
    const int n0 = blockIdx.x * 256;
    const int T = K >> 4;

    // fill-path addressing
    const int arow0 = tid >> 2,  acol4 = (tid & 3) << 2;    // + it*64 rows
    const int brow0 = tid >> 6,  bcol4 = (tid & 63) << 2;   // + it*4 rows

    float acc[4][8][4];
    #pragma unroll
    for (int i = 0; i < 4; i++)
        #pragma unroll
        for (int j = 0; j < 8; j++)
            #pragma unroll
            for (int r = 0; r < 4; r++) acc[i][j][r] = 0.f;

    float4 pa[2], pb[4];

    // ---- prologue: tile 0 -> regs -> stage0; tile 1 -> regs ----
    #pragma unroll
    for (int it = 0; it < 2; it++)
        pa[it] = *(const float4*)(A + (size_t)(m0 + arow0 + it * 64) * lda + acol4);
    #pragma unroll
    for (int it = 0; it < 4; it++)
        pb[it] = *(const float4*)(B + (size_t)(brow0 + it * 4) * ldb + n0 + bcol4);
    #pragma unroll
    for (int it = 0; it < 2; it++)
        *(uint4*)&AsS[0][(arow0 + it * 64) * 20 + acol4] = make_uint4(
            tf32_of(pa[it].x), tf32_of(pa[it].y), tf32_of(pa[it].z), tf32_of(pa[it].w));
    #pragma unroll
    for (int it = 0; it < 4; it++)
        *(uint4*)&BsS[0][(brow0 + it * 4) * 264 + bcol4] = make_uint4(
            tf32_of(pb[it].x), tf32_of(pb[it].y), tf32_of(pb[it].z), tf32_of(pb[it].w));
    if (T > 1) {
        #pragma unroll
        for (int it = 0; it < 2; it++)
            pa[it] = *(const float4*)(A + (size_t)(m0 + arow0 + it * 64) * lda + 16 + acol4);
        #pragma unroll
        for (int it = 0; it < 4; it++)
            pb[it] = *(const float4*)(B + (size_t)(16 + brow0 + it * 4) * ldb + n0 + bcol4);
    }
    __syncthreads();

    for (int t = 0; t < T; t++) {
        const unsigned* Asc = AsS[t & 1];
        const unsigned* Bsc = BsS[t & 1];
        // store prefetched tile t+1 into the other stage
        if (t + 1 < T) {
            unsigned* Asn = AsS[(t + 1) & 1];
            unsigned* Bsn = BsS[(t + 1) & 1];
            #pragma unroll
            for (int it = 0; it < 2; it++)
                *(uint4*)&Asn[(arow0 + it * 64) * 20 + acol4] = make_uint4(
                    tf32_of(pa[it].x), tf32_of(pa[it].y), tf32_of(pa[it].z), tf32_of(pa[it].w));
            #pragma unroll
            for (int it = 0; it < 4; it++)
                *(uint4*)&Bsn[(brow0 + it * 4) * 264 + bcol4] = make_uint4(
                    tf32_of(pb[it].x), tf32_of(pb[it].y), tf32_of(pb[it].z), tf32_of(pb[it].w));
        }
        // issue LDG for tile t+2
        if (t + 2 < T) {
            int k0 = (t + 2) * 16;
            #pragma unroll
            for (int it = 0; it < 2; it++)
                pa[it] = *(const float4*)(A + (size_t)(m0 + arow0 + it * 64) * lda + k0 + acol4);
            #pragma unroll
            for (int it = 0; it < 4; it++)
                pb[it] = *(const float4*)(B + (size_t)(k0 + brow0 + it * 4) * ldb + n0 + bcol4);
        }
        // compute current stage
        #pragma unroll
        for (int kk = 0; kk < 16; kk += 8) {
            unsigned afr[4][4], bfr[8][2];
            #pragma unroll
            for (int i = 0; i < 4; i++) {
                int mm = warp_m + i * 16 + gid;
                afr[i][0] = Asc[mm * 20 + kk + tig];
                afr[i][1] = Asc[(mm + 8) * 20 + kk + tig];
                afr[i][2] = Asc[mm * 20 + kk + tig + 4];
                afr[i][3] = Asc[(mm + 8) * 20 + kk + tig + 4];
            }
            #pragma unroll
            for (int j = 0; j < 8; j++) {
                int nn = warp_n + j * 8 + gid;
                bfr[j][0] = Bsc[(kk + tig) * 264 + nn];
                bfr[j][1] = Bsc[(kk + tig + 4) * 264 + nn];
            }
            #pragma unroll
            for (int i = 0; i < 4; i++)
                #pragma unroll
                for (int j = 0; j < 8; j++) mma_tf32(acc[i][j], afr[i], bfr[j]);
        }
        __syncthreads();
    }

    // ---- epilogue: bias add, store, fused reductions ----
    const bool do_cs = (colsum_out != nullptr);
    const bool do_qd = (qdp_out != nullptr);
    float ss = 0.f;
    float qd[4][2];
    #pragma unroll
    for (int i = 0; i < 4; i++) { qd[i][0] = 0.f; qd[i][1] = 0.f; }

    #pragma unroll
    for (int j = 0; j < 8; j++) {
        int c = n0 + warp_n + j * 8 + tig * 2;
        float bx = bias ? bias[c] : 0.f;
        float by = bias ? bias[c + 1] : 0.f;
        float ks0 = 0.f, ks1 = 0.f;
        if (do_qd) { ks0 = ksvec[c]; ks1 = ksvec[c + 1]; }
        float cs0 = 0.f, cs1 = 0.f;
        #pragma unroll
        for (int i = 0; i < 4; i++) {
            int r = m0 + warp_m + i * 16 + gid;
            float x0 = acc[i][j][0] + bx, x1 = acc[i][j][1] + by;
            float x2 = acc[i][j][2] + bx, x3 = acc[i][j][3] + by;
            *(float2*)(C + (size_t)r * ldc + c)       = make_float2(x0, x1);
            *(float2*)(C + (size_t)(r + 8) * ldc + c) = make_float2(x2, x3);
            ss += x0 * x0 + x1 * x1 + x2 * x2 + x3 * x3;
            cs0 += x0 + x2; cs1 += x1 + x3;
            qd[i][0] += x0 * ks0 + x1 * ks1;
            qd[i][1] += x2 * ks0 + x3 * ks1;
        }
        if (do_cs) {
            epism[(tid * 8 + j) * 2 + 0] = cs0;
            epism[(tid * 8 + j) * 2 + 1] = cs1;
        }
    }

    if (do_cs) {
        __syncthreads();
        int c = tid;
        int wn = c >> 6, j = (c >> 3) & 7, tg = (c & 7) >> 1, e = c & 1;
        float s = 0.f;
        #pragma unroll
        for (int wm = 0; wm < 2; wm++)
            #pragma unroll
            for (int g = 0; g < 8; g++) {
                int t2 = (2 * wn + wm) * 32 + g * 4 + tg;
                s += epism[(t2 * 8 + j) * 2 + e];
            }
        colsum_out[(size_t)blockIdx.y * 1024 + n0 + c] = s;
    }

    if (do_qd) {
        __syncthreads();
        #pragma unroll
        for (int i = 0; i < 4; i++) {
            epism[(tid * 4 + i) * 2 + 0] = qd[i][0];
            epism[(tid * 4 + i) * 2 + 1] = qd[i][1];
        }
        __syncthreads();
        if (tid < 128) {
            int rl = tid;
            int wm = rl >> 6, rem = rl & 63;
            int i = rem >> 4, hf = (rem >> 3) & 1, g = rem & 7;
            float s = 0.f;
            #pragma unroll
            for (int wn = 0; wn < 4; wn++)
                #pragma unroll
                for (int tg = 0; tg < 4; tg++) {
                    int t2 = (2 * wn + wm) * 32 + g * 4 + tg;
                    s += epism[(t2 * 4 + i) * 2 + hf];
                }
            qdp_out[(size_t)blockIdx.x * 65536u + m0 + rl] = s;
        }
    }

    if (ss_out) {
        float s = block_reduce_sum(ss, rsm);
        if (tid == 0) ss_out[blockIdx.y * gridDim.x + blockIdx.x] = s;
    }
}

// ---------------------------------------------------------------------------
// Fused attention GEMM (v3 double-buffered core):
//   C[r,c] (+)= 0.5 * inv[r] * ( (A@B)[r,c] * s  +  65536 * V[r,c] )
// ---------------------------------------------------------------------------
__global__ __launch_bounds__(256) void gemm_attn_v3(
    const float* __restrict__ A, const float* __restrict__ B,
    const float* __restrict__ Vb, const float* __restrict__ invp,
    const float* __restrict__ scal, float* __restrict__ C, int beta)
{
    extern __shared__ unsigned dsm[];
    unsigned* AsS[2] = { dsm,        dsm + 2560 };
    unsigned* BsS[2] = { dsm + 5120, dsm + 5120 + 4224 };

    const int tid = threadIdx.x;
    const int lane = tid & 31;
    const int wid = tid >> 5;
    const int gid = lane >> 2, tig = lane & 3;
    const int warp_m = (wid & 1) * 64;
    const int warp_n = (wid >> 1) * 64;
    const int m0 = blockIdx.y * 128;
    const int n0 = blockIdx.x * 256;
    const int T = 32;   // K=512

    const int arow0 = tid >> 2,  acol4 = (tid & 3) << 2;
    const int brow0 = tid >> 6,  bcol4 = (tid & 63) << 2;

    float acc[4][8][4];
    #pragma unroll
    for (int i = 0; i < 4; i++)
        #pragma unroll
        for (int j = 0; j < 8; j++)
            #pragma unroll
            for (int r = 0; r < 4; r++) acc[i][j][r] = 0.f;

    float4 pa[2], pb[4];
    #pragma unroll
    for (int it = 0; it < 2; it++)
        pa[it] = *(const float4*)(A + (size_t)(m0 + arow0 + it * 64) * 1024 + acol4);
    #pragma unroll
    for (int it = 0; it < 4; it++)
        pb[it] = *(const float4*)(B + (size_t)(brow0 + it * 4) * 512 + n0 + bcol4);
    #pragma unroll
    for (int it = 0; it < 2; it++)
        *(uint4*)&AsS[0][(arow0 + it * 64) * 20 + acol4] = make_uint4(
            tf32_of(pa[it].x), tf32_of(pa[it].y), tf32_of(pa[it].z), tf32_of(pa[it].w));
    #pragma unroll
    for (int it = 0; it < 4; it++)
        *(uint4*)&BsS[0][(brow0 + it * 4) * 264 + bcol4] = make_uint4(
            tf32_of(pb[it].x), tf32_of(pb[it].y), tf32_of(pb[it].z), tf32_of(pb[it].w));
    #pragma unroll
    for (int it = 0; it < 2; it++)
        pa[it] = *(const float4*)(A + (size_t)(m0 + arow0 + it * 64) * 1024 + 16 + acol4);
    #pragma unroll
    for (int it = 0; it < 4; it++)
        pb[it] = *(const float4*)(B + (size_t)(16 + brow0 + it * 4) * 512 + n0 + bcol4);
    __syncthreads();

    for (int t = 0; t < T; t++) {
        const unsigned* Asc = AsS[t & 1];
        const unsigned* Bsc = BsS[t & 1];
        if (t + 1 < T) {
            unsigned* Asn = AsS[(t + 1) & 1];
            unsigned* Bsn = BsS[(t + 1) & 1];
            #pragma unroll
            for (int it = 0; it < 2; it++)
                *(uint4*)&Asn[(arow0 + it * 64) * 20 + acol4] = make_uint4(
                    tf32_of(pa[it].x), tf32_of(pa[it].y), tf32_of(pa[it].z), tf32_of(pa[it].w));
            #pragma unroll
            for (int it = 0; it < 4; it++)
                *(uint4*)&Bsn[(brow0 + it * 4) * 264 + bcol4] = make_uint4(
                    tf32_of(pb[it].x), tf32_of(pb[it].y), tf32_of(pb[it].z), tf32_of(pb[it].w));
        }
        if (t + 2 < T) {
            int k0 = (t + 2) * 16;
            #pragma unroll
            for (int it = 0; it < 2; it++)
                pa[it] = *(const float4*)(A + (size_t)(m0 + arow0 + it * 64) * 1024 + k0 + acol4);
            #pragma unroll
            for (int it = 0; it < 4; it++)
                pb[it] = *(const float4*)(B + (size_t)(k0 + brow0 + it * 4) * 512 + n0 + bcol4);
        }
        #pragma unroll
        for (int kk = 0; kk < 16; kk += 8) {
            unsigned afr[4][4], bfr[8][2];
            #pragma unroll
            for (int i = 0; i < 4; i++) {
                int mm = warp_m + i * 16 + gid;
                afr[i][0] = Asc[mm * 20 + kk + tig];
                afr[i][1] = Asc[(mm + 8) * 20 + kk + tig];
                afr[i][2] = Asc[mm * 20 + kk + tig + 4];
                afr[i][3] = Asc[(mm + 8) * 20 + kk + tig + 4];
            }
            #pragma unroll
            for (int j = 0; j < 8; j++) {
                int nn = warp_n + j * 8 + gid;
                bfr[j][0] = Bsc[(kk + tig) * 264 + nn];
                bfr[j][1] = Bsc[(kk + tig + 4) * 264 + nn];
            }
            #pragma unroll
            for (int i = 0; i < 4; i++)
                #pragma unroll
                for (int j = 0; j < 8; j++) mma_tf32(acc[i][j], afr[i], bfr[j]);
        }
        __syncthreads();
    }

    const float s = rsqrtf(scal[0] * scal[1]);   // 1/(||q||*||k||)
    #pragma unroll
    for (int j = 0; j < 8; j++) {
        int c = n0 + warp_n + j * 8 + tig * 2;
        #pragma unroll
        for (int i = 0; i < 4; i++) {
            int r = m0 + warp_m + i * 16 + gid;
            float iv0 = invp[2 * (size_t)r];
            float iv1 = invp[2 * (size_t)(r + 8)];
            float2 va  = *(const float2*)(Vb + (size_t)r * 1024 + c);
            float2 vbv = *(const float2*)(Vb + (size_t)(r + 8) * 1024 + c);
            float x0 = (acc[i][j][0] * s + 65536.f * va.x)  * iv0 * 0.5f;
            float x1 = (acc[i][j][1] * s + 65536.f * va.y)  * iv0 * 0.5f;
            float x2 = (acc[i][j][2] * s + 65536.f * vbv.x) * iv1 * 0.5f;
            float x3 = (acc[i][j][3] * s + 65536.f * vbv.y) * iv1 * 0.5f;
            float* c0 = C + (size_t)r * 1024 + c;
            float* c1 = C + (size_t)(r + 8) * 1024 + c;
            if (beta) {
                float2 o0 = *(float2*)c0, o1 = *(float2*)c1;
                x0 += o0.x; x1 += o0.y; x2 += o1.x; x3 += o1.y;
            }
            *(float2*)c0 = make_float2(x0, x1);
            *(float2*)c1 = make_float2(x2, x3);
        }
    }
}

// ---------------------------------------------------------------------------
// TN GEMM for kvs (v3 double-buffered): C[m,d] = sum_l K[l,m]*V[l,d], split-K.
// As [16][136] per stage, Bs [16][264] per stage.
// ---------------------------------------------------------------------------
__global__ __launch_bounds__(256) void gemm_tn_kv_v3(
    const float* __restrict__ Kp, const float* __restrict__ Vp,
    float* __restrict__ part)
{
    extern __shared__ unsigned dsm[];
    unsigned* AsS[2] = { dsm,        dsm + 2176 };          // [16][136]
    unsigned* BsS[2] = { dsm + 4352, dsm + 4352 + 4224 };   // [16][264]

    const int tid = threadIdx.x;
    const int lane = tid & 31;
    const int wid = tid >> 5;
    const int gid = lane >> 2, tig = lane & 3;
    const int warp_m = (wid & 1) * 64;
    const int warp_n = (wid >> 1) * 64;
    const int d0 = blockIdx.x * 256;
    const int m0 = blockIdx.y * 128;
    const int h  = blockIdx.z >> 4;
    const int sp = blockIdx.z & 15;
    const int CH = NPTS / KVSPL;       // 4096
    const int T = CH >> 4;             // 256

    const float* Ab = Kp + (size_t)h * 512;
    const float* Bb = Vp + (size_t)h * 512;
    const int lbeg = sp * CH;

    const int alrow = tid >> 5, amcol4 = (tid & 31) << 2;  // + it*8 rows
    const int blrow = tid >> 6, bdcol4 = (tid & 63) << 2;  // + it*4 rows

    float acc[4][8][4];
    #pragma unroll
    for (int i = 0; i < 4; i++)
        #pragma unroll
        for (int j = 0; j < 8; j++)
            #pragma unroll
            for (int r = 0; r < 4; r++) acc[i][j][r] = 0.f;

    float4 pa[2], pb[4];
    #pragma unroll
    for (int it = 0; it < 2; it++)
        pa[it] = *(const float4*)(Ab + (size_t)(lbeg + alrow + it * 8) * 1024 + m0 + amcol4);
    #pragma unroll
    for (int it = 0; it < 4; it++)
        pb[it] = *(const float4*)(Bb + (size_t)(lbeg + blrow + it * 4) * 1024 + d0 + bdcol4);
    #pragma unroll
    for (int it = 0; it < 2; it++)
        *(uint4*)&AsS[0][(alrow + it * 8) * 136 + amcol4] = make_uint4(
            tf32_of(pa[it].x), tf32_of(pa[it].y), tf32_of(pa[it].z), tf32_of(pa[it].w));
    #pragma unroll
    for (int it = 0; it < 4; it++)
        *(uint4*)&BsS[0][(blrow + it * 4) * 264 + bdcol4] = make_uint4(
            tf32_of(pb[it].x), tf32_of(pb[it].y), tf32_of(pb[it].z), tf32_of(pb[it].w));
    #pragma unroll
    for (int it = 0; it < 2; it++)
        pa[it] = *(const float4*)(Ab + (size_t)(lbeg + 16 + alrow + it * 8) * 1024 + m0 + amcol4);
    #pragma unroll
    for (int it = 0; it < 4; it++)
        pb[it] = *(const float4*)(Bb + (size_t)(lbeg + 16 + blrow + it * 4) * 1024 + d0 + bdcol4);
    __syncthreads();

    for (int t = 0; t < T; t++) {
        const unsigned* Asc = AsS[t & 1];
        const unsigned* Bsc = BsS[t & 1];
        if (t + 1 < T) {
            unsigned* Asn = AsS[(t + 1) & 1];
            unsigned* Bsn = BsS[(t + 1) & 1];
            #pragma unroll
            for (int it = 0; it < 2; it++)
                *(uint4*)&Asn[(alrow + it * 8) * 136 + amcol4] = make_uint4(
                    tf32_of(pa[it].x), tf32_of(pa[it].y), tf32_of(pa[it].z), tf32_of(pa[it].w));
            #pragma unroll
            for (int it = 0; it < 4; it++)
                *(uint4*)&Bsn[(blrow + it * 4) * 264 + bdcol4] = make_uint4(
                    tf32_of(pb[it].x), tf32_of(pb[it].y), tf32_of(pb[it].z), tf32_of(pb[it].w));
        }
        if (t + 2 < T) {
            int l0 = lbeg + (t + 2) * 16;
            #pragma unroll
            for (int it = 0; it < 2; it++)
                pa[it] = *(const float4*)(Ab + (size_t)(l0 + alrow + it * 8) * 1024 + m0 + amcol4);
            #pragma unroll
            for (int it = 0; it < 4; it++)
                pb[it] = *(const float4*)(Bb + (size_t)(l0 + blrow + it * 4) * 1024 + d0 + bdcol4);
        }
        #pragma unroll
        for (int kk = 0; kk < 16; kk += 8) {
            unsigned afr[4][4], bfr[8][2];
            #pragma unroll
            for (int i = 0; i < 4; i++) {
                int mm = warp_m + i * 16 + gid;
                afr[i][0] = Asc[(kk + tig) * 136 + mm];
                afr[i][1] = Asc[(kk + tig) * 136 + mm + 8];
                afr[i][2] = Asc[(kk + tig + 4) * 136 + mm];
                afr[i][3] = Asc[(kk + tig + 4) * 136 + mm + 8];
            }
            #pragma unroll
            for (int j = 0; j < 8; j++) {
                int nn = warp_n + j * 8 + gid;
                bfr[j][0] = Bsc[(kk + tig) * 264 + nn];
                bfr[j][1] = Bsc[(kk + tig + 4) * 264 + nn];
            }
            #pragma unroll
            for (int i = 0; i < 4; i++)
                #pragma unroll
                for (int j = 0; j < 8; j++) mma_tf32(acc[i][j], afr[i], bfr[j]);
        }
        __syncthreads();
    }

    float* P = part + (size_t)blockIdx.z * 262144u;
    #pragma unroll
    for (int j = 0; j < 8; j++) {
        int c = d0 + warp_n + j * 8 + tig * 2;
        #pragma unroll
        for (int i = 0; i < 4; i++) {
            int r = m0 + warp_m + i * 16 + gid;
            *(float2*)(P + (size_t)r * 512 + c)       = make_float2(acc[i][j][0], acc[i][j][1]);
            *(float2*)(P + (size_t)(r + 8) * 512 + c) = make_float2(acc[i][j][2], acc[i][j][3]);
        }
    }
}

__global__ void kv_reduce(const float* __restrict__ part, float* __restrict__ kvs) {
    int idx = blockIdx.x * 256 + threadIdx.x;          // 0..524287
    int h = idx >> 18;
    int i = idx & 262143;
    const float* p = part + (size_t)(h * KVSPL) * 262144u + i;
    float s = 0.f;
    #pragma unroll
    for (int sp = 0; sp < KVSPL; sp++) s += p[(size_t)sp * 262144u];
    kvs[idx] = s;
}

// ---------------------------------------------------------------------------
// Deterministic scalar reduce of n partials
// ---------------------------------------------------------------------------
__global__ __launch_bounds__(256) void reduce_to_scalar(
    const float* __restrict__ part, int n, float* __restrict__ out)
{
    __shared__ float sm[8];
    float s = 0.f;
    for (int i = threadIdx.x; i < n; i += 256) s += part[i];
    s = block_reduce_sum(s, sm);
    if (threadIdx.x == 0) *out = s;
}

// ---------------------------------------------------------------------------
// ks[col] = sum over 512 per-block partials (from K-proj epilogue)
// ---------------------------------------------------------------------------
__global__ __launch_bounds__(256) void ks_reduce512(
    const float* __restrict__ ksp, float* __restrict__ out)
{
    int col = blockIdx.x * 256 + threadIdx.x;   // grid = 4
    float s = 0.f;
    for (int by = 0; by < 512; by++) s += ksp[(size_t)by * 1024 + col];
    out[col] = s;
}

// ---------------------------------------------------------------------------
// inv from qdp partials
// ---------------------------------------------------------------------------
__global__ __launch_bounds__(256) void inv_from_qdp(
    const float* __restrict__ qdp, const float* __restrict__ scal,
    float* __restrict__ inv)
{
    int n = blockIdx.x * 256 + threadIdx.x;     // grid = 256
    float s = rsqrtf(scal[0] * scal[1]);
    float qd0 = qdp[n] + qdp[65536u + n];
    float qd1 = qdp[2u * 65536u + n] + qdp[3u * 65536u + n];
    inv[2 * n]     = 1.0f / (qd0 * s + 65536.0f);
    inv[2 * n + 1] = 1.0f / (qd1 * s + 65536.0f);
}

// ---------------------------------------------------------------------------
// fc0 epilogue: LayerNorm + ReLU, one block per row
// ---------------------------------------------------------------------------
__global__ __launch_bounds__(256) void ln_relu(
    const float* __restrict__ x, const float* __restrict__ g,
    const float* __restrict__ b, float* __restrict__ out)
{
    __shared__ float sm[8];
    int n = blockIdx.x, t = threadIdx.x;
    size_t r = (size_t)n * 512;
    float v0 = x[r + t], v1 = x[r + 256 + t];
    float mu = block_reduce_sum(v0 + v1, sm) * (1.f / 512.f);
    float d0 = v0 - mu, d1 = v1 - mu;
    float var = block_reduce_sum(d0 * d0 + d1 * d1, sm) * (1.f / 512.f);
    float rs = rsqrtf(var + 1e-5f);
    float o0 = d0 * rs * g[t] + b[t];
    float o1 = d1 * rs * g[t + 256] + b[t + 256];
    out[r + t]       = fmaxf(o0, 0.f);
    out[r + 256 + t] = fmaxf(o1, 0.f);
}

// ---------------------------------------------------------------------------
// Residual + LayerNorm: out = LN(0.5*attn + 0.5*prev). attn has ld 1024.
// ---------------------------------------------------------------------------
__global__ __launch_bounds__(256) void combine_res_ln(
    const float* __restrict__ attn, const float* __restrict__ prev,
    const float* __restrict__ g, const float* __restrict__ b,
    float* __restrict__ out)
{
    __shared__ float sm[8];
    int n = blockIdx.x, t = threadIdx.x;
    size_t r1 = (size_t)n * 1024;
    size_t r5 = (size_t)n * 512;
    float val0 = 0.5f * attn[r1 + t]       + 0.5f * prev[r5 + t];
    float val1 = 0.5f * attn[r1 + 256 + t] + 0.5f * prev[r5 + 256 + t];
    float mu = block_reduce_sum(val0 + val1, sm) * (1.f / 512.f);
    float d0 = val0 - mu, d1 = val1 - mu;
    float var = block_reduce_sum(d0 * d0 + d1 * d1, sm) * (1.f / 512.f);
    float rs = rsqrtf(var + 1e-5f);
    out[r5 + t]       = d0 * rs * g[t] + b[t];
    out[r5 + 256 + t] = d1 * rs * g[t + 256] + b[t + 256];
}

// ---------------------------------------------------------------------------
// Launch
// ---------------------------------------------------------------------------
extern "C" void kernel_launch(void* const* d_in, const int* in_sizes, int n_in,
                              void* d_out, int out_size)
{
    (void)in_sizes; (void)n_in; (void)out_size;
    const float* x     = (const float*)d_in[0];
    const float* fc0_w = (const float*)d_in[1];
    const float* fc0_b = (const float*)d_in[2];
    const float* ln0_g = (const float*)d_in[3];
    const float* ln0_b = (const float*)d_in[4];
    const float* wq    = (const float*)d_in[5];
    const float* bq    = (const float*)d_in[6];
    const float* wk    = (const float*)d_in[7];
    const float* bk    = (const float*)d_in[8];
    const float* wv    = (const float*)d_in[9];
    const float* bv    = (const float*)d_in[10];
    const float* lng   = (const float*)d_in[11];
    const float* lnb   = (const float*)d_in[12];
    float* out = (float*)d_out;

    float *qk, *v, *hbuf, *kvp, *kvs, *ksp, *ks, *red, *scal, *qdp, *inv;
    cudaGetSymbolAddress((void**)&qk,   g_qk);
    cudaGetSymbolAddress((void**)&v,    g_v);
    cudaGetSymbolAddress((void**)&hbuf, g_h);
    cudaGetSymbolAddress((void**)&kvp,  g_kvp);
    cudaGetSymbolAddress((void**)&kvs,  g_kvs);
    cudaGetSymbolAddress((void**)&ksp,  g_ksp);
    cudaGetSymbolAddress((void**)&ks,   g_ks);
    cudaGetSymbolAddress((void**)&red,  g_red);
    cudaGetSymbolAddress((void**)&scal, g_scal);
    cudaGetSymbolAddress((void**)&qdp,  g_qdp);
    cudaGetSymbolAddress((void**)&inv,  g_inv);

    // opt-in to >48KB dynamic smem (idempotent; not a stream op)
    static bool attr_done = false;
    if (!attr_done) {
        cudaFuncSetAttribute(gemm_nn_v3,
            cudaFuncAttributeMaxDynamicSharedMemorySize, SMEM_NN);
        cudaFuncSetAttribute(gemm_attn_v3,
            cudaFuncAttributeMaxDynamicSharedMemorySize, SMEM_NN);
        cudaFuncSetAttribute(gemm_tn_kv_v3,
            cudaFuncAttributeMaxDynamicSharedMemorySize, SMEM_KV);
        attr_done = true;
    }

    dim3 thr(256);

    // --- input projection: h = relu(LN(x @ fc0_w + fc0_b)) ---
    gemm_nn_v3<<<dim3(2, 512), thr, SMEM_NN>>>(x, fc0_w, fc0_b, v,
                                      NPTS, 512, 512, 512, 512, 512,
                                      nullptr, nullptr, nullptr, nullptr);
    ln_relu<<<NPTS, thr>>>(v, ln0_g, ln0_b, hbuf);

    for (int L = 0; L < 2; L++) {
        const float* prev = L ? out : hbuf;
        float* lout = out;                       // layer 1 in-place (row-local)
        const float* WQ  = wq + (size_t)L * 512 * 1024;
        const float* WK  = wk + (size_t)L * 512 * 1024;
        const float* WV  = wv + (size_t)L * 512 * 1024;
        const float* BQ  = bq + (size_t)L * 1024;
        const float* BKb = bk + (size_t)L * 1024;
        const float* BV  = bv + (size_t)L * 1024;

        // V projection
        gemm_nn_v3<<<dim3(4, 512), thr, SMEM_NN>>>(prev, WV, BV, v,
                                          NPTS, HH, HID, 512, 1024, 1024,
                                          nullptr, nullptr, nullptr, nullptr);
        // K projection (+ ss partials, + column-sum partials)
        gemm_nn_v3<<<dim3(4, 512), thr, SMEM_NN>>>(prev, WK, BKb, qk,
                                          NPTS, HH, HID, 512, 1024, 1024,
                                          red + 4096, ksp, nullptr, nullptr);
        reduce_to_scalar<<<1, thr>>>(red + 4096, 2048, scal + 1);
        ks_reduce512<<<4, thr>>>(ksp, ks);

        // kvs = K^T V per head (split-K, deterministic)
        gemm_tn_kv_v3<<<dim3(2, 4, 32), thr, SMEM_KV>>>(qk, v, kvp);
        kv_reduce<<<2048, thr>>>(kvp, kvs);

        // Q projection overwrites K (K dead) (+ ss partials, + q.ks partials)
        gemm_nn_v3<<<dim3(4, 512), thr, SMEM_NN>>>(prev, WQ, BQ, qk,
                                          NPTS, HH, HID, 512, 1024, 1024,
                                          red, nullptr, ks, qdp);
        reduce_to_scalar<<<1, thr>>>(red, 2048, scal + 0);

        // per-row denominators from fused partials
        inv_from_qdp<<<256, thr>>>(qdp, scal, inv);

        // fused Q@kvs + attention combine; attn aliases V's head-0 half
        gemm_attn_v3<<<dim3(2, 512), thr, SMEM_NN>>>(qk, kvs, v, inv, scal, v, 0);
        gemm_attn_v3<<<dim3(2, 512), thr, SMEM_NN>>>(qk + 512, kvs + 262144u,
                                            v + 512, inv + 1, scal, v, 1);

        // residual + LN
        combine_res_ln<<<NPTS, thr>>>(v, prev,
                                      lng + (size_t)L * 512, lnb + (size_t)L * 512,
                                      lout);
    }
}